// round 13
// baseline (speedup 1.0000x reference)
#include <cuda_runtime.h>
#include <cuda_bf16.h>
#include <cstdint>

// ManeuverHead on GB300 — 2 kernels, raw mma.sync pipeline, warp-pair split-N.
//  k_front: persistent fused front end (grid barriers): init + masked scans +
//           boundary cbase + scatter + w1/w2 staged in EXACT mma fragment order.
//  k_main : 1024 blocks x 128 threads (4 warps = 2 pairs). Each PAIR owns one
//           16-slot strip; warp A does n-tiles 0..7, warp B 8..15 (128 MMAs
//           each). Layer 2 split along K; partials summed via 1KB smem.
// N=262144, B=4096, D=128, G=8, R=7.

#define NNODES   262144
#define NB       4096
#define GG       8
#define RR       7
#define NSLOTS   (NB * GG)
#define NEGV     (-1e9f)
#define FGRID    256

// ---------------- device scratch ------------------------------------------
__device__ int          d_blockSums[FGRID];
__device__ int          d_blockOff[FGRID];
__device__ int          d_cbase[NB];
__device__ int          d_slotNode[NSLOTS];
__device__ uint2        d_w1frag[8192];   // 256 tiles (kt 0..15, nt 0..15) x 32 lanes
__device__ uint2        d_w2frag[256];    // 8 k-tiles x 32 lanes (w2 padded to 8 cols)
__device__ unsigned int g_cnt;            // zero-init
__device__ volatile unsigned int g_gen;   // zero-init

__device__ __forceinline__ unsigned int pk_bf2(float x, float y) {
    __nv_bfloat162 p = __floats2bfloat162_rn(x, y);
    return *reinterpret_cast<unsigned int*>(&p);
}

// ---------------- K1: fused front end --------------------------------------
__global__ void __launch_bounds__(256)
k_front(const int* __restrict__ mask, const int* __restrict__ batch,
        const float* __restrict__ w1, const float* __restrict__ w2) {
    int t = threadIdx.x, bid = blockIdx.x;
    int lane = t & 31, warp = t >> 5;
    int gid = bid * 256 + t;

    __shared__ int ws[8];
    __shared__ unsigned int s_gen;
    __shared__ int s_lead;

    // ---- P0: aux init + fragment-order weight staging ----
    if (gid < NSLOTS) d_slotNode[gid] = -1;
    if (gid < 8192) {                       // w1 fragments (m16n8k16 B layout)
        int tile = gid >> 5, fl = gid & 31;
        int kt = tile >> 4, nt = tile & 15;
        int q = fl & 3, g = fl >> 2;
        int k0 = kt * 16 + 2 * q;
        int n  = nt * 8 + g;
        uint2 v;
        v.x = pk_bf2(w1[k0 * 128 + n],        w1[(k0 + 1) * 128 + n]);
        v.y = pk_bf2(w1[(k0 + 8) * 128 + n],  w1[(k0 + 9) * 128 + n]);
        d_w1frag[gid] = v;
    }
    if (gid < 256) {                        // w2 fragments (padded to 8 cols)
        int kt2 = gid >> 5, fl = gid & 31;
        int q = fl & 3, g = fl >> 2;
        int k0 = kt2 * 16 + 2 * q;
        float w00 = (g < RR) ? w2[k0 * RR + g]       : 0.f;
        float w01 = (g < RR) ? w2[(k0 + 1) * RR + g] : 0.f;
        float w10 = (g < RR) ? w2[(k0 + 8) * RR + g] : 0.f;
        float w11 = (g < RR) ? w2[(k0 + 9) * RR + g] : 0.f;
        uint2 v;
        v.x = pk_bf2(w00, w01);
        v.y = pk_bf2(w10, w11);
        d_w2frag[gid] = v;
    }

    // ---- P0: block scan of masked flags ----
    int4 m = ((const int4*)mask)[gid];
    int4 b = ((const int4*)batch)[gid];
    int g0 = m.x != 0, g1 = m.y != 0, g2 = m.z != 0, g3 = m.w != 0;
    int s = g0 + g1 + g2 + g3;
    int inc = s;
#pragma unroll
    for (int o = 1; o < 32; o <<= 1) {
        int v = __shfl_up_sync(~0u, inc, o);
        if (lane >= o) inc += v;
    }
    if (lane == 31) ws[warp] = inc;
    __syncthreads();
    if (warp == 0 && lane < 8) {
        int v = ws[lane], iv = v;
#pragma unroll
        for (int o = 1; o < 8; o <<= 1) {
            int x = __shfl_up_sync(0xffu, iv, o);
            if (lane >= o) iv += x;
        }
        ws[lane] = iv - v;
        if (lane == 7) d_blockSums[bid] = iv;
    }
    __syncthreads();
    int lexcl = ws[warp] + (inc - s);

    // ---- BAR1: leader scans blockSums -> blockOff ----
    __threadfence();
    __syncthreads();
    if (t == 0) {
        s_gen = g_gen;
        unsigned int a = atomicAdd(&g_cnt, 1u);
        s_lead = (a == (unsigned)gridDim.x - 1u);
    }
    __syncthreads();
    if (s_lead) {
        __threadfence();
        int v = d_blockSums[t];
        int iv = v;
#pragma unroll
        for (int o = 1; o < 32; o <<= 1) {
            int x = __shfl_up_sync(~0u, iv, o);
            if (lane >= o) iv += x;
        }
        if (lane == 31) ws[warp] = iv;
        __syncthreads();
        if (warp == 0 && lane < 8) {
            int v2 = ws[lane], iv2 = v2;
#pragma unroll
            for (int o = 1; o < 8; o <<= 1) {
                int x = __shfl_up_sync(0xffu, iv2, o);
                if (lane >= o) iv2 += x;
            }
            ws[lane] = iv2 - v2;
        }
        __syncthreads();
        d_blockOff[t] = ws[warp] + (iv - v);
        __threadfence();
        __syncthreads();
        if (t == 0) {
            *(volatile unsigned int*)&g_cnt = 0u;
            __threadfence();
            g_gen = s_gen + 1u;
        }
    } else {
        if (t == 0) {
            while (g_gen == s_gen) __nanosleep(64);
            __threadfence();
        }
        __syncthreads();
    }

    // ---- P2: boundary nodes write cbase ----
    int pe0 = d_blockOff[bid] + lexcl;
    int pw = __shfl_up_sync(~0u, b.w, 1);
    int prevb = (lane == 0) ? ((gid > 0) ? batch[gid * 4 - 1] : -1) : pw;
    {
        int pe = pe0;
        if (b.x != prevb) d_cbase[b.x] = pe;  pe += g0;
        if (b.y != b.x)   d_cbase[b.y] = pe;  pe += g1;
        if (b.z != b.y)   d_cbase[b.z] = pe;  pe += g2;
        if (b.w != b.z)   d_cbase[b.w] = pe;
    }

    // ---- BAR2 ----
    __threadfence();
    __syncthreads();
    if (t == 0) {
        s_gen = g_gen;
        unsigned int a = atomicAdd(&g_cnt, 1u);
        s_lead = (a == (unsigned)gridDim.x - 1u);
    }
    __syncthreads();
    if (s_lead) {
        if (t == 0) {
            *(volatile unsigned int*)&g_cnt = 0u;
            __threadfence();
            g_gen = s_gen + 1u;
        }
        __syncthreads();
    } else {
        if (t == 0) {
            while (g_gen == s_gen) __nanosleep(64);
            __threadfence();
        }
        __syncthreads();
    }

    // ---- P3: scatter ----
    int base = gid * 4;
    int pre = pe0;
    if (g0) { int r = pre - d_cbase[b.x]; if (r < GG) d_slotNode[b.x * GG + r] = base;     pre++; }
    if (g1) { int r = pre - d_cbase[b.y]; if (r < GG) d_slotNode[b.y * GG + r] = base + 1; pre++; }
    if (g2) { int r = pre - d_cbase[b.z]; if (r < GG) d_slotNode[b.z * GG + r] = base + 2; pre++; }
    if (g3) { int r = pre - d_cbase[b.w]; if (r < GG) d_slotNode[b.w * GG + r] = base + 3; }
}

// ---------------- K2: main — warp-pair mma.sync pipeline --------------------
// 1024 blocks x 128 threads (4 warps = 2 pairs). Pair p owns 16 slots
// (strip p); warp half h = w&1 computes n-tiles h*8..h*8+7 and layer-2
// k2 tiles h*4..h*4+3. Partial layer-2 results summed via smem.
#define STRIP_BYTES 8448
#define OFF_DRED    (2 * STRIP_BYTES)          // float[2][32][4]
#define MAIN_SMEM_BYTES (OFF_DRED + 1024)

__device__ __forceinline__ void mma16816(float& c0, float& c1, float& c2, float& c3,
                                         unsigned a0, unsigned a1, unsigned a2, unsigned a3,
                                         unsigned b0, unsigned b1) {
    asm volatile(
        "mma.sync.aligned.m16n8k16.row.col.f32.bf16.bf16.f32 "
        "{%0,%1,%2,%3}, {%4,%5,%6,%7}, {%8,%9}, {%0,%1,%2,%3};"
        : "+f"(c0), "+f"(c1), "+f"(c2), "+f"(c3)
        : "r"(a0), "r"(a1), "r"(a2), "r"(a3), "r"(b0), "r"(b1));
}

__global__ void __launch_bounds__(128, 8)
k_main(const float* __restrict__ nf,
       const float* __restrict__ gf,
       const float* __restrict__ b1,
       const float* __restrict__ b2,
       const int* __restrict__ mvm,
       float* __restrict__ out) {
    extern __shared__ __align__(16) unsigned char sm[];
    int t = threadIdx.x, w = t >> 5, lane = t & 31;
    int p = w >> 1, h = w & 1;                     // pair, half
    unsigned char* strip = sm + p * STRIP_BYTES;
    float* dred = (float*)(sm + OFF_DRED) + p * 128;   // [32][4] per pair

    int gp = blockIdx.x * 2 + p;                   // global pair id
    int slot0 = gp * 16;
    int b0w   = gp * 2;                            // 2 batches per pair

    int nd = (lane < 16) ? d_slotNode[slot0 + lane] : -1;

    // ---- cooperative gather: 16 rows x 64 float4-units -> bf16 strip ----
    {
        const float4* nf4 = (const float4*)nf;
        const float4* gf4 = (const float4*)gf;
        const float4 z = make_float4(0.f, 0.f, 0.f, 0.f);
#pragma unroll
        for (int i = lane + h * 32; i < 1024; i += 64) {
            int row = i >> 6, c4 = i & 63;
            float4 v;
            if (c4 < 32) {
                int ndr = __shfl_sync(~0u, nd, row);
                v = (ndr >= 0) ? nf4[ndr * 32 + c4] : z;
            } else {
                v = gf4[(b0w + (row >> 3)) * 32 + (c4 - 32)];
            }
            uint2 pk;
            pk.x = pk_bf2(v.x, v.y);
            pk.y = pk_bf2(v.z, v.w);
            *(uint2*)(strip + row * 528 + c4 * 8) = pk;
        }
    }
    __syncthreads();                               // both strips complete

    // ---- layer 1: C[j] (j=0..7, nt = h*8+j) = A(16x256) @ w1 fragments ----
    unsigned int smaddr;
    asm("{ .reg .u64 tt; cvta.to.shared.u64 tt, %1; cvt.u32.u64 %0, tt; }"
        : "=r"(smaddr) : "l"(strip));
    unsigned int lmrow = (lane & 7) + ((lane >> 3) & 1) * 8;
    unsigned int lmaddr = smaddr + lmrow * 528 + (lane >> 4) * 16;

    float c[8][4];
#pragma unroll
    for (int j = 0; j < 8; j++)
#pragma unroll
        for (int k = 0; k < 4; k++) c[j][k] = 0.f;

#pragma unroll 1
    for (int kt = 0; kt < 16; kt++) {
        unsigned a0, a1, a2, a3;
        asm volatile("ldmatrix.sync.aligned.m8n8.x4.shared.b16 {%0,%1,%2,%3}, [%4];"
                     : "=r"(a0), "=r"(a1), "=r"(a2), "=r"(a3)
                     : "r"(lmaddr + kt * 32));
        const uint2* fb = d_w1frag + kt * 16 * 32 + h * 8 * 32 + lane;
#pragma unroll
        for (int j = 0; j < 8; j++) {
            uint2 bv = fb[j * 32];
            mma16816(c[j][0], c[j][1], c[j][2], c[j][3],
                     a0, a1, a2, a3, bv.x, bv.y);
        }
    }

    // ---- layer 2 partial: this warp owns k2 = h*4 .. h*4+3 ----
    int q = lane & 3, g = lane >> 2;
    float d0 = 0.f, d1 = 0.f, d2 = 0.f, d3 = 0.f;
#pragma unroll
    for (int j2 = 0; j2 < 4; j2++) {
        int k2 = h * 4 + j2;                       // global k2 tile
        float2 ba = *(const float2*)(b1 + k2 * 16 + 2 * q);
        float2 bb = *(const float2*)(b1 + k2 * 16 + 8 + 2 * q);
        unsigned A0 = pk_bf2(fmaxf(c[2 * j2][0] + ba.x, 0.f),
                             fmaxf(c[2 * j2][1] + ba.y, 0.f));
        unsigned A1 = pk_bf2(fmaxf(c[2 * j2][2] + ba.x, 0.f),
                             fmaxf(c[2 * j2][3] + ba.y, 0.f));
        unsigned A2 = pk_bf2(fmaxf(c[2 * j2 + 1][0] + bb.x, 0.f),
                             fmaxf(c[2 * j2 + 1][1] + bb.y, 0.f));
        unsigned A3 = pk_bf2(fmaxf(c[2 * j2 + 1][2] + bb.x, 0.f),
                             fmaxf(c[2 * j2 + 1][3] + bb.y, 0.f));
        uint2 bv = d_w2frag[k2 * 32 + lane];
        mma16816(d0, d1, d2, d3, A0, A1, A2, A3, bv.x, bv.y);
    }

    // ---- cross-warp reduction of layer-2 partials ----
    if (h == 1) {
        float4 dv = make_float4(d0, d1, d2, d3);
        *(float4*)(dred + lane * 4) = dv;
    }
    __syncthreads();

    if (h == 0) {
        float4 dv = *(const float4*)(dred + lane * 4);
        d0 += dv.x; d1 += dv.y; d2 += dv.z; d3 += dv.w;

        // ---- masked output: c0,c1 = row g cols 2q,2q+1; c2,c3 = row g+8 ----
        int r0c = 2 * q, r1c = 2 * q + 1;
        float b2v0 = b2[r0c];
        float b2v1 = (r1c < RR) ? b2[r1c] : 0.f;
#pragma unroll
        for (int half = 0; half < 2; half++) {
            int m = g + half * 8;
            float v0 = half ? d2 : d0;
            float v1 = half ? d3 : d1;
            int occ = __shfl_sync(~0u, nd, m) >= 0;
            int bb2 = b0w + (m >> 3);
            int orow = bb2 * (GG * RR) + (m & 7) * RR;
            out[orow + r0c] = (occ && mvm[orow + r0c] != 0) ? v0 + b2v0 : NEGV;
            if (r1c < RR)
                out[orow + r1c] = (occ && mvm[orow + r1c] != 0) ? v1 + b2v1 : NEGV;
        }
    }
}

// ---------------- launch ---------------------------------------------------
extern "C" void kernel_launch(void* const* d_in, const int* in_sizes, int n_in,
                              void* d_out, int out_size) {
    const float* nf    = (const float*)d_in[0];
    const float* gf    = (const float*)d_in[1];
    const int*   gmask = (const int*)d_in[2];
    const int*   mvm   = (const int*)d_in[3];
    const int*   batch = (const int*)d_in[4];
    const float* w1    = (const float*)d_in[5];
    const float* b1    = (const float*)d_in[6];
    const float* w2    = (const float*)d_in[7];
    const float* b2    = (const float*)d_in[8];
    float*       out   = (float*)d_out;

    cudaFuncSetAttribute(k_main, cudaFuncAttributeMaxDynamicSharedMemorySize,
                         MAIN_SMEM_BYTES);

    k_front<<<FGRID, 256>>>(gmask, batch, w1, w2);
    k_main<<<1024, 128, MAIN_SMEM_BYTES>>>(nf, gf, b1, b2, mvm, out);
}

// round 14
// speedup vs baseline: 1.5619x; 1.5619x over previous
#include <cuda_runtime.h>
#include <cuda_bf16.h>
#include <cstdint>

// ManeuverHead on GB300 — 2 kernels, raw mma.sync pipeline (R12 base +
// deep-MLP batched gather).
//  k_front: persistent fused front end (grid barriers): init + masked scans +
//           boundary cbase + scatter + w1/w2 staged in EXACT mma fragment order.
//  k_main : 512 blocks x 128 threads; each warp fully owns 16 slots (2 batches):
//           batched gather (16 LDG.128 in flight) -> ldmatrix -> 256x
//           mma.m16n8k16 (bf16, K=256) -> in-register relu+b1 -> layer-2 mma
//           -> masked STG. No __syncthreads.
// N=262144, B=4096, D=128, G=8, R=7.

#define NNODES   262144
#define NB       4096
#define GG       8
#define RR       7
#define NSLOTS   (NB * GG)
#define NEGV     (-1e9f)
#define FGRID    256

// ---------------- device scratch ------------------------------------------
__device__ int          d_blockSums[FGRID];
__device__ int          d_blockOff[FGRID];
__device__ int          d_cbase[NB];
__device__ int          d_slotNode[NSLOTS];
__device__ uint2        d_w1frag[8192];   // 256 tiles (kt 0..15, nt 0..15) x 32 lanes
__device__ uint2        d_w2frag[256];    // 8 k-tiles x 32 lanes (w2 padded to 8 cols)
__device__ unsigned int g_cnt;            // zero-init
__device__ volatile unsigned int g_gen;   // zero-init

__device__ __forceinline__ unsigned int pk_bf2(float x, float y) {
    __nv_bfloat162 p = __floats2bfloat162_rn(x, y);
    return *reinterpret_cast<unsigned int*>(&p);
}

// ---------------- K1: fused front end --------------------------------------
__global__ void __launch_bounds__(256)
k_front(const int* __restrict__ mask, const int* __restrict__ batch,
        const float* __restrict__ w1, const float* __restrict__ w2) {
    int t = threadIdx.x, bid = blockIdx.x;
    int lane = t & 31, warp = t >> 5;
    int gid = bid * 256 + t;

    __shared__ int ws[8];
    __shared__ unsigned int s_gen;
    __shared__ int s_lead;

    // ---- P0: aux init + fragment-order weight staging ----
    if (gid < NSLOTS) d_slotNode[gid] = -1;
    if (gid < 8192) {                       // w1 fragments (m16n8k16 B layout)
        int tile = gid >> 5, fl = gid & 31;
        int kt = tile >> 4, nt = tile & 15;
        int q = fl & 3, g = fl >> 2;
        int k0 = kt * 16 + 2 * q;
        int n  = nt * 8 + g;
        uint2 v;
        v.x = pk_bf2(w1[k0 * 128 + n],        w1[(k0 + 1) * 128 + n]);
        v.y = pk_bf2(w1[(k0 + 8) * 128 + n],  w1[(k0 + 9) * 128 + n]);
        d_w1frag[gid] = v;
    }
    if (gid < 256) {                        // w2 fragments (padded to 8 cols)
        int kt2 = gid >> 5, fl = gid & 31;
        int q = fl & 3, g = fl >> 2;
        int k0 = kt2 * 16 + 2 * q;
        float w00 = (g < RR) ? w2[k0 * RR + g]       : 0.f;
        float w01 = (g < RR) ? w2[(k0 + 1) * RR + g] : 0.f;
        float w10 = (g < RR) ? w2[(k0 + 8) * RR + g] : 0.f;
        float w11 = (g < RR) ? w2[(k0 + 9) * RR + g] : 0.f;
        uint2 v;
        v.x = pk_bf2(w00, w01);
        v.y = pk_bf2(w10, w11);
        d_w2frag[gid] = v;
    }

    // ---- P0: block scan of masked flags ----
    int4 m = ((const int4*)mask)[gid];
    int4 b = ((const int4*)batch)[gid];
    int g0 = m.x != 0, g1 = m.y != 0, g2 = m.z != 0, g3 = m.w != 0;
    int s = g0 + g1 + g2 + g3;
    int inc = s;
#pragma unroll
    for (int o = 1; o < 32; o <<= 1) {
        int v = __shfl_up_sync(~0u, inc, o);
        if (lane >= o) inc += v;
    }
    if (lane == 31) ws[warp] = inc;
    __syncthreads();
    if (warp == 0 && lane < 8) {
        int v = ws[lane], iv = v;
#pragma unroll
        for (int o = 1; o < 8; o <<= 1) {
            int x = __shfl_up_sync(0xffu, iv, o);
            if (lane >= o) iv += x;
        }
        ws[lane] = iv - v;
        if (lane == 7) d_blockSums[bid] = iv;
    }
    __syncthreads();
    int lexcl = ws[warp] + (inc - s);

    // ---- BAR1: leader scans blockSums -> blockOff ----
    __threadfence();
    __syncthreads();
    if (t == 0) {
        s_gen = g_gen;
        unsigned int a = atomicAdd(&g_cnt, 1u);
        s_lead = (a == (unsigned)gridDim.x - 1u);
    }
    __syncthreads();
    if (s_lead) {
        __threadfence();
        int v = d_blockSums[t];
        int iv = v;
#pragma unroll
        for (int o = 1; o < 32; o <<= 1) {
            int x = __shfl_up_sync(~0u, iv, o);
            if (lane >= o) iv += x;
        }
        if (lane == 31) ws[warp] = iv;
        __syncthreads();
        if (warp == 0 && lane < 8) {
            int v2 = ws[lane], iv2 = v2;
#pragma unroll
            for (int o = 1; o < 8; o <<= 1) {
                int x = __shfl_up_sync(0xffu, iv2, o);
                if (lane >= o) iv2 += x;
            }
            ws[lane] = iv2 - v2;
        }
        __syncthreads();
        d_blockOff[t] = ws[warp] + (iv - v);
        __threadfence();
        __syncthreads();
        if (t == 0) {
            *(volatile unsigned int*)&g_cnt = 0u;
            __threadfence();
            g_gen = s_gen + 1u;
        }
    } else {
        if (t == 0) {
            while (g_gen == s_gen) __nanosleep(64);
            __threadfence();
        }
        __syncthreads();
    }

    // ---- P2: boundary nodes write cbase ----
    int pe0 = d_blockOff[bid] + lexcl;
    int pw = __shfl_up_sync(~0u, b.w, 1);
    int prevb = (lane == 0) ? ((gid > 0) ? batch[gid * 4 - 1] : -1) : pw;
    {
        int pe = pe0;
        if (b.x != prevb) d_cbase[b.x] = pe;  pe += g0;
        if (b.y != b.x)   d_cbase[b.y] = pe;  pe += g1;
        if (b.z != b.y)   d_cbase[b.z] = pe;  pe += g2;
        if (b.w != b.z)   d_cbase[b.w] = pe;
    }

    // ---- BAR2 ----
    __threadfence();
    __syncthreads();
    if (t == 0) {
        s_gen = g_gen;
        unsigned int a = atomicAdd(&g_cnt, 1u);
        s_lead = (a == (unsigned)gridDim.x - 1u);
    }
    __syncthreads();
    if (s_lead) {
        if (t == 0) {
            *(volatile unsigned int*)&g_cnt = 0u;
            __threadfence();
            g_gen = s_gen + 1u;
        }
        __syncthreads();
    } else {
        if (t == 0) {
            while (g_gen == s_gen) __nanosleep(64);
            __threadfence();
        }
        __syncthreads();
    }

    // ---- P3: scatter ----
    int base = gid * 4;
    int pre = pe0;
    if (g0) { int r = pre - d_cbase[b.x]; if (r < GG) d_slotNode[b.x * GG + r] = base;     pre++; }
    if (g1) { int r = pre - d_cbase[b.y]; if (r < GG) d_slotNode[b.y * GG + r] = base + 1; pre++; }
    if (g2) { int r = pre - d_cbase[b.z]; if (r < GG) d_slotNode[b.z * GG + r] = base + 2; pre++; }
    if (g3) { int r = pre - d_cbase[b.w]; if (r < GG) d_slotNode[b.w * GG + r] = base + 3; }
}

// ---------------- K2: main — warp-autonomous mma.sync pipeline --------------
// 512 blocks x 128 threads (4 warps). Warp strip: 16 rows x 264 bf16 (528 B
// row stride -> ldmatrix conflict-free), cols 0..127 node feats, 128..255
// globals. Gather uses two 16-deep LDG.128 batches for high MLP.
#define STRIP_BYTES 8448
#define MAIN_SMEM_BYTES (4 * STRIP_BYTES)

__device__ __forceinline__ void mma16816(float& c0, float& c1, float& c2, float& c3,
                                         unsigned a0, unsigned a1, unsigned a2, unsigned a3,
                                         unsigned b0, unsigned b1) {
    asm volatile(
        "mma.sync.aligned.m16n8k16.row.col.f32.bf16.bf16.f32 "
        "{%0,%1,%2,%3}, {%4,%5,%6,%7}, {%8,%9}, {%0,%1,%2,%3};"
        : "+f"(c0), "+f"(c1), "+f"(c2), "+f"(c3)
        : "r"(a0), "r"(a1), "r"(a2), "r"(a3), "r"(b0), "r"(b1));
}

__global__ void __launch_bounds__(128, 4)
k_main(const float* __restrict__ nf,
       const float* __restrict__ gf,
       const float* __restrict__ b1,
       const float* __restrict__ b2,
       const int* __restrict__ mvm,
       float* __restrict__ out) {
    extern __shared__ __align__(16) unsigned char sm[];
    int t = threadIdx.x, w = t >> 5, lane = t & 31;
    unsigned char* strip = sm + w * STRIP_BYTES;

    int slot0 = (blockIdx.x * 4 + w) * 16;
    int b0w   = (blockIdx.x * 4 + w) * 2;          // 2 batches per warp

    int nd = (lane < 16) ? d_slotNode[slot0 + lane] : -1;

    // ---- gather: 16 rows x 64 float4-units, two 16-deep load batches ----
    {
        const float4* nf4 = (const float4*)nf;
        const float4* gf4 = (const float4*)gf;
        const float4 z = make_float4(0.f, 0.f, 0.f, 0.f);
#pragma unroll
        for (int bb = 0; bb < 2; bb++) {
            float4 v[16];
#pragma unroll
            for (int j = 0; j < 16; j++) {
                int i = lane + (bb * 16 + j) * 32;
                int row = i >> 6, c4 = i & 63;
                if (c4 < 32) {
                    int ndr = __shfl_sync(~0u, nd, row);
                    v[j] = (ndr >= 0) ? nf4[ndr * 32 + c4] : z;
                } else {
                    v[j] = gf4[(b0w + (row >> 3)) * 32 + (c4 - 32)];
                }
            }
#pragma unroll
            for (int j = 0; j < 16; j++) {
                int i = lane + (bb * 16 + j) * 32;
                int row = i >> 6, c4 = i & 63;
                uint2 pk;
                pk.x = pk_bf2(v[j].x, v[j].y);
                pk.y = pk_bf2(v[j].z, v[j].w);
                *(uint2*)(strip + row * 528 + c4 * 8) = pk;
            }
        }
    }
    __syncwarp();

    // ---- layer 1: C[nt] (nt=0..15) = A(16x256) @ w1 fragments ----
    unsigned int smaddr;
    asm("{ .reg .u64 tt; cvta.to.shared.u64 tt, %1; cvt.u32.u64 %0, tt; }"
        : "=r"(smaddr) : "l"(strip));
    unsigned int lmrow = (lane & 7) + ((lane >> 3) & 1) * 8;
    unsigned int lmaddr = smaddr + lmrow * 528 + (lane >> 4) * 16;

    float c[16][4];
#pragma unroll
    for (int nt = 0; nt < 16; nt++)
#pragma unroll
        for (int j = 0; j < 4; j++) c[nt][j] = 0.f;

#pragma unroll 1
    for (int kt = 0; kt < 16; kt++) {
        unsigned a0, a1, a2, a3;
        asm volatile("ldmatrix.sync.aligned.m8n8.x4.shared.b16 {%0,%1,%2,%3}, [%4];"
                     : "=r"(a0), "=r"(a1), "=r"(a2), "=r"(a3)
                     : "r"(lmaddr + kt * 32));
        const uint2* fb = d_w1frag + kt * 16 * 32 + lane;
#pragma unroll
        for (int nt = 0; nt < 16; nt++) {
            uint2 bv = fb[nt * 32];
            mma16816(c[nt][0], c[nt][1], c[nt][2], c[nt][3],
                     a0, a1, a2, a3, bv.x, bv.y);
        }
    }

    // ---- layer 2: in-register relu+b1 -> bf16 A fragments -> mma ----
    int q = lane & 3, g = lane >> 2;
    float d0 = 0.f, d1 = 0.f, d2 = 0.f, d3 = 0.f;
#pragma unroll
    for (int k2 = 0; k2 < 8; k2++) {
        float2 ba = *(const float2*)(b1 + k2 * 16 + 2 * q);
        float2 bb = *(const float2*)(b1 + k2 * 16 + 8 + 2 * q);
        unsigned A0 = pk_bf2(fmaxf(c[2 * k2][0] + ba.x, 0.f),
                             fmaxf(c[2 * k2][1] + ba.y, 0.f));
        unsigned A1 = pk_bf2(fmaxf(c[2 * k2][2] + ba.x, 0.f),
                             fmaxf(c[2 * k2][3] + ba.y, 0.f));
        unsigned A2 = pk_bf2(fmaxf(c[2 * k2 + 1][0] + bb.x, 0.f),
                             fmaxf(c[2 * k2 + 1][1] + bb.y, 0.f));
        unsigned A3 = pk_bf2(fmaxf(c[2 * k2 + 1][2] + bb.x, 0.f),
                             fmaxf(c[2 * k2 + 1][3] + bb.y, 0.f));
        uint2 bv = d_w2frag[k2 * 32 + lane];
        mma16816(d0, d1, d2, d3, A0, A1, A2, A3, bv.x, bv.y);
    }

    // ---- masked output: fc2 c0,c1 = row g cols 2q,2q+1; c2,c3 = row g+8 ----
    {
        int r0c = 2 * q, r1c = 2 * q + 1;
        float b2v0 = b2[r0c];                       // r0c in {0,2,4,6} < 7
        float b2v1 = (r1c < RR) ? b2[r1c] : 0.f;
#pragma unroll
        for (int half = 0; half < 2; half++) {
            int m = g + half * 8;
            float v0 = half ? d2 : d0;
            float v1 = half ? d3 : d1;
            int occ = __shfl_sync(~0u, nd, m) >= 0;
            int bb2 = b0w + (m >> 3);
            int orow = bb2 * (GG * RR) + (m & 7) * RR;
            out[orow + r0c] = (occ && mvm[orow + r0c] != 0) ? v0 + b2v0 : NEGV;
            if (r1c < RR)
                out[orow + r1c] = (occ && mvm[orow + r1c] != 0) ? v1 + b2v1 : NEGV;
        }
    }
}

// ---------------- launch ---------------------------------------------------
extern "C" void kernel_launch(void* const* d_in, const int* in_sizes, int n_in,
                              void* d_out, int out_size) {
    const float* nf    = (const float*)d_in[0];
    const float* gf    = (const float*)d_in[1];
    const int*   gmask = (const int*)d_in[2];
    const int*   mvm   = (const int*)d_in[3];
    const int*   batch = (const int*)d_in[4];
    const float* w1    = (const float*)d_in[5];
    const float* b1    = (const float*)d_in[6];
    const float* w2    = (const float*)d_in[7];
    const float* b2    = (const float*)d_in[8];
    float*       out   = (float*)d_out;

    cudaFuncSetAttribute(k_main, cudaFuncAttributeMaxDynamicSharedMemorySize,
                         MAIN_SMEM_BYTES);

    k_front<<<FGRID, 256>>>(gmask, batch, w1, w2);
    k_main<<<512, 128, MAIN_SMEM_BYTES>>>(nf, gf, b1, b2, mvm, out);
}